// round 8
// baseline (speedup 1.0000x reference)
#include <cuda_runtime.h>
#include <cstdint>

// Problem shapes (fixed by the dataset)
#define ROWS      16384
#define PRED_COLS 100
#define TRUE_COLS 50
#define KK        50
#define TPB       256
#define WPB       (TPB / 32)        // 8 warps = 8 rows per block
#define NBLOCKS   (ROWS / WPB)      // 2048
#define FULL      0xFFFFFFFFu

// Scratch (allocation-free per harness rules)
__device__ float        g_partials[NBLOCKS];
__device__ unsigned int g_count = 0;   // reset by last block -> graph-replay-safe

__global__ __launch_bounds__(TPB) void mapk_warp_kernel(
    const int*   __restrict__ y_pred,
    const int*   __restrict__ y_true,
    const float* __restrict__ mult,
    float*       __restrict__ out)
{
    __shared__ unsigned int bmT[WPB][32];   // per-warp membership bitmap of trues
    __shared__ unsigned int bmP[WPB][32];   // per-warp bitmap of LOW preds (pos 0..31)
    __shared__ float red[WPB];
    __shared__ unsigned int s_prev;

    const int tid  = threadIdx.x;
    const int w    = tid >> 5;
    const int lane = tid & 31;
    const bool hiv = (lane < KK - 32);      // lanes 0..17 hold the high halves

    const int row = blockIdx.x * WPB + w;
    const int* __restrict__ tr = y_true + (size_t)row * TRUE_COLS;
    const int* __restrict__ pr = y_pred + (size_t)row * PRED_COLS;

    // ---- coalesced loads (6 LDG, all independent) ----
    int   t0  = tr[lane];
    int   t1  = hiv ? tr[32 + lane] : -1;
    int   p0  = pr[lane];
    int   p1  = hiv ? pr[32 + lane] : -1;
    float ml0 = mult[lane];                 // lane < 32 < KK, always valid
    float ml1 = hiv ? mult[32 + lane] : 0.0f;

    const unsigned int lt = (1u << lane) - 1u;     // lanes strictly below
    const unsigned int le = (2u << lane) - 1u;     // lanes <= (wraps to ~0 at lane 31)

    // ---- zero both bitmaps (1 STS each; lane l owns word l) ----
    bmT[w][lane] = 0u;
    bmP[w][lane] = 0u;
    __syncwarp();

    // ---- build bitmaps: match_any groups lanes by word index, redux ORs
    //      the bits in-register, lowest lane of each group stores. No atomics. ----
    {   // trues, first 32
        unsigned int wd = ((unsigned)t0 >> 5) & 31u;
        unsigned int g  = __match_any_sync(FULL, wd);
        unsigned int v  = __reduce_or_sync(g, 1u << (t0 & 31));
        if ((g & lt) == 0u) bmT[w][wd] = v;        // leader of group
    }
    {   // low preds (positions 0..31)
        unsigned int wd = ((unsigned)p0 >> 5) & 31u;
        unsigned int g  = __match_any_sync(FULL, wd);
        unsigned int v  = __reduce_or_sync(g, 1u << (p0 & 31));
        if ((g & lt) == 0u) bmP[w][wd] = v;
    }
    __syncwarp();
    {   // trues, last 18 (sentinel lanes contribute 0 bits)
        unsigned int wd = ((unsigned)t1 >> 5) & 31u;
        unsigned int g  = __match_any_sync(FULL, wd);
        unsigned int v  = __reduce_or_sync(g, hiv ? (1u << (t1 & 31)) : 0u);
        if (((g & lt) == 0u) && v) bmT[w][wd] |= v;   // OR-merge, race-free
    }
    __syncwarp();

    // ---- membership + dup, fully branch-free ----
    unsigned int match0 = (bmT[w][((unsigned)p0 >> 5) & 31u] >> (p0 & 31)) & 1u;
    unsigned int match1 = hiv ? ((bmT[w][((unsigned)p1 >> 5) & 31u] >> (p1 & 31)) & 1u) : 0u;
    unsigned int cross1 = hiv ? ((bmP[w][((unsigned)p1 >> 5) & 31u] >> (p1 & 31)) & 1u) : 0u;

    unsigned int g0 = __match_any_sync(FULL, p0);   // equal-value groups, low half
    unsigned int g1 = __match_any_sync(FULL, p1);   // high half (sentinels group, masked out)
    bool dup0 = (g0 & lt) != 0u;                    // earlier equal low pred
    bool dup1 = ((g1 & lt) != 0u) | (cross1 != 0u); // earlier-high or any-low equal

    bool hit0 = match0 && !dup0;
    bool hit1 = match1 && !dup1;
    unsigned int hitlo = __ballot_sync(FULL, hit0);
    unsigned int hithi = __ballot_sync(FULL, hit1);

    // ---- closed-form AP contribution per lane, then warp reduction ----
    int   nlo = __popc(hitlo);
    float c   = 0.0f;
    if (hit0) c += (float)__popc(hitlo & le) * ml0;
    if (hit1) c += (float)(nlo + __popc(hithi & le)) * ml1;

    #pragma unroll
    for (int off = 16; off > 0; off >>= 1)
        c += __shfl_down_sync(FULL, c, off);

    // ---- block reduction (deterministic) + fused finalize ----
    if (lane == 0) red[w] = c;
    __syncthreads();
    if (w == 0) {
        float v = (lane < WPB) ? red[lane] : 0.0f;
        #pragma unroll
        for (int off = WPB / 2; off > 0; off >>= 1)
            v += __shfl_down_sync(FULL, v, off);
        if (lane == 0) {
            g_partials[blockIdx.x] = v;
            __threadfence();
            s_prev = atomicAdd(&g_count, 1u);
        }
    }
    __syncthreads();

    if (s_prev == NBLOCKS - 1) {   // last block: deterministic final reduction
        __threadfence();
        float v = 0.0f;
        #pragma unroll
        for (int k = 0; k < NBLOCKS / TPB; ++k)   // 8 fixed-stride terms per thread
            v += g_partials[tid + k * TPB];
        #pragma unroll
        for (int off = 16; off > 0; off >>= 1)
            v += __shfl_down_sync(FULL, v, off);
        if (lane == 0) red[w] = v;
        __syncthreads();
        if (tid == 0) {
            float s = 0.0f;
            #pragma unroll
            for (int k = 0; k < WPB; ++k) s += red[k];
            out[0] = s * (1.0f / ((float)TRUE_COLS * (float)ROWS));
            g_count = 0;   // reset for next graph replay
        }
    }
}

extern "C" void kernel_launch(void* const* d_in, const int* in_sizes, int n_in,
                              void* d_out, int out_size)
{
    // Assign inputs by element count (robust to metadata ordering)
    const int*   y_pred = nullptr;
    const int*   y_true = nullptr;
    const float* mult   = nullptr;
    for (int i = 0; i < n_in; ++i) {
        if      (in_sizes[i] == ROWS * PRED_COLS) y_pred = (const int*)d_in[i];
        else if (in_sizes[i] == ROWS * TRUE_COLS) y_true = (const int*)d_in[i];
        else if (in_sizes[i] == KK)               mult   = (const float*)d_in[i];
    }
    float* out = (float*)d_out;

    mapk_warp_kernel<<<NBLOCKS, TPB>>>(y_pred, y_true, mult, out);
}

// round 9
// speedup vs baseline: 3.2801x; 3.2801x over previous
#include <cuda_runtime.h>
#include <cstdint>

// Problem shapes (fixed by the dataset)
#define ROWS      16384
#define PRED_COLS 100
#define TRUE_COLS 50
#define KK        50
#define TPB       256
#define WPB       (TPB / 32)        // 8 warps = 8 rows per block
#define NBLOCKS   (ROWS / WPB)      // 2048
#define FULL      0xFFFFFFFFu

// Scratch (allocation-free per harness rules)
__device__ float        g_partials[NBLOCKS];
__device__ unsigned int g_count = 0;   // reset by last block -> graph-replay-safe

__global__ __launch_bounds__(TPB) void mapk_warp_kernel(
    const int*   __restrict__ y_pred,
    const int*   __restrict__ y_true,
    const float* __restrict__ mult,
    float*       __restrict__ out)
{
    __shared__ unsigned int bmT[WPB][32];   // per-warp 1024-bit membership bitmap
    __shared__ float red[WPB];
    __shared__ unsigned int s_prev;

    const int tid  = threadIdx.x;
    const int w    = tid >> 5;
    const int lane = tid & 31;
    const bool hiv = (lane < KK - 32);      // lanes 0..17 hold the high halves

    const int row = blockIdx.x * WPB + w;
    const int* __restrict__ tr = y_true + (size_t)row * TRUE_COLS;
    const int* __restrict__ pr = y_pred + (size_t)row * PRED_COLS;

    // ---- coalesced loads (6 LDG, all independent) ----
    int   t0  = tr[lane];
    int   t1  = hiv ? tr[32 + lane] : -1;
    int   p0  = pr[lane];
    int   p1  = hiv ? pr[32 + lane] : -1;     // sentinel: tests an always-0 bit
    float ml0 = mult[lane];                    // lane < 32 < KK, always valid
    float ml1 = hiv ? mult[32 + lane] : 0.0f;

    // ---- build bitmap: zero own word, 2 spread-address atomicOr ----
    bmT[w][lane] = 0u;
    __syncwarp();
    atomicOr(&bmT[w][((unsigned)t0 >> 5) & 31u], 1u << (t0 & 31));
    if (t1 >= 0)
        atomicOr(&bmT[w][((unsigned)t1 >> 5) & 31u], 1u << (t1 & 31));
    __syncwarp();

    // ---- bitmap into registers: lane i owns word i (conflict-free LDS) ----
    unsigned int myword = bmT[w][lane];

    // ---- membership via dynamic-source shfl (no random-bank LDS) ----
    unsigned int w0  = __shfl_sync(FULL, myword, ((unsigned)p0 >> 5));
    unsigned int w1  = __shfl_sync(FULL, myword, ((unsigned)p1 >> 5));
    bool m0 = (w0 >> (p0 & 31)) & 1u;
    bool m1 = (w1 >> (p1 & 31)) & 1u;         // sentinel -1 -> word31 bit31 = 0
    unsigned int mlo = __ballot_sync(FULL, m0);
    unsigned int mhi = __ballot_sync(FULL, m1);

    // ---- uniform scoring: process matched positions earliest-first;
    //      on scoring value v, clear ALL equal positions (both halves) ->
    //      duplicates can never be scored. All lanes compute identical score. ----
    float cnt = 0.0f, score = 0.0f;
    while (mlo) {
        int i = __ffs((int)mlo) - 1;
        int   v = __shfl_sync(FULL, p0, i);
        float f = __shfl_sync(FULL, ml0, i);
        unsigned int eqlo = __ballot_sync(FULL, p0 == v);
        unsigned int eqhi = __ballot_sync(FULL, p1 == v);
        mlo &= ~eqlo;                          // clears bit i + all low dups
        mhi &= ~eqhi;                          // clears all high dups
        cnt += 1.0f;
        score += cnt * f;
    }
    while (mhi) {
        int i = __ffs((int)mhi) - 1;
        int   v = __shfl_sync(FULL, p1, i);
        float f = __shfl_sync(FULL, ml1, i);
        unsigned int eqhi = __ballot_sync(FULL, p1 == v);
        mhi &= ~eqhi;                          // clears bit i + all high dups
        cnt += 1.0f;
        score += cnt * f;
    }

    // ---- score is warp-uniform: lane 0 publishes; block reduce; finalize ----
    if (lane == 0) red[w] = score;
    __syncthreads();
    if (w == 0) {
        float v = (lane < WPB) ? red[lane] : 0.0f;
        #pragma unroll
        for (int off = WPB / 2; off > 0; off >>= 1)
            v += __shfl_down_sync(FULL, v, off);
        if (lane == 0) {
            g_partials[blockIdx.x] = v;
            __threadfence();
            s_prev = atomicAdd(&g_count, 1u);
        }
    }
    __syncthreads();

    if (s_prev == NBLOCKS - 1) {   // last block: deterministic final reduction
        __threadfence();
        float v = 0.0f;
        #pragma unroll
        for (int k = 0; k < NBLOCKS / TPB; ++k)   // 8 fixed-stride terms per thread
            v += g_partials[tid + k * TPB];
        #pragma unroll
        for (int off = 16; off > 0; off >>= 1)
            v += __shfl_down_sync(FULL, v, off);
        if (lane == 0) red[w] = v;
        __syncthreads();
        if (tid == 0) {
            float s = 0.0f;
            #pragma unroll
            for (int k = 0; k < WPB; ++k) s += red[k];
            out[0] = s * (1.0f / ((float)TRUE_COLS * (float)ROWS));
            g_count = 0;   // reset for next graph replay
        }
    }
}

extern "C" void kernel_launch(void* const* d_in, const int* in_sizes, int n_in,
                              void* d_out, int out_size)
{
    // Assign inputs by element count (robust to metadata ordering)
    const int*   y_pred = nullptr;
    const int*   y_true = nullptr;
    const float* mult   = nullptr;
    for (int i = 0; i < n_in; ++i) {
        if      (in_sizes[i] == ROWS * PRED_COLS) y_pred = (const int*)d_in[i];
        else if (in_sizes[i] == ROWS * TRUE_COLS) y_true = (const int*)d_in[i];
        else if (in_sizes[i] == KK)               mult   = (const float*)d_in[i];
    }
    float* out = (float*)d_out;

    mapk_warp_kernel<<<NBLOCKS, TPB>>>(y_pred, y_true, mult, out);
}